// round 13
// baseline (speedup 1.0000x reference)
#include <cuda_runtime.h>
#include <cuda_fp16.h>
#include <math.h>
#include <stdint.h>

constexpr int B_  = 16;
constexpr int H_  = 1024;
constexpr int CO_ = 512;
constexpr int NV_ = 2048;
constexpr int NQ_ = 2048;

// packed (uint32 = 2 fp16) operand sizes, per-batch counts
constexpr size_t PQ  = (size_t)(NQ_/2) * H_;
constexpr size_t PQT = (size_t)(H_/2) * NQ_;
constexpr size_t PV  = (size_t)(H_/2) * NV_;
constexpr size_t PVT = (size_t)(NV_/2) * H_;
constexpr size_t PW  = (size_t)(H_/2) * H_;
constexpr size_t PWC = (size_t)(H_/2) * CO_;
constexpr size_t PNC = (size_t)(NQ_/2) * CO_;
constexpr size_t PHC = (size_t)(H_/2) * CO_;

__device__ uint32_t g_Qp  [PQ  * B_], g_Qph [PQ  * B_];
__device__ uint32_t g_Qtp [PQT * B_], g_Qtph[PQT * B_];
__device__ uint32_t g_Vp  [PV  * B_], g_Vph [PV  * B_];
__device__ uint32_t g_Vtp [PVT * B_], g_Vtph[PVT * B_];
__device__ uint32_t g_Wbp [PW], g_Wbph[PW], g_Wbtp[PW], g_Wbtph[PW];
__device__ uint32_t g_WqTp[PWC], g_WqTph[PWC], g_WvTp[PWC], g_WvTph[PWC];
__device__ uint32_t g_T1p [PNC * B_], g_T1ph[PNC * B_];
__device__ uint32_t g_T2p [PNC * B_], g_T2ph[PNC * B_];
__device__ uint32_t g_PvTp[PHC * B_], g_PvTph[PHC * B_];
__device__ uint32_t g_PqTp[PHC * B_], g_PqTph[PHC * B_];
__device__ uint32_t g_RvTp[PHC * B_], g_RvTph[PHC * B_];
__device__ uint32_t g_RqTp[PHC * B_], g_RqTph[PHC * B_];

__device__ float g_lpart[(size_t)2 * B_ * 4 * 2048];   // partial logits
__device__ float g_logv_unused;                        // (kept none)
__device__ float g_part[(size_t)B_ * 16 * H_];

__device__ __forceinline__ uint32_t smem_u32(const void* p) {
    uint32_t a;
    asm("{ .reg .u64 t; cvta.to.shared.u64 t, %1; cvt.u32.u64 %0, t; }" : "=r"(a) : "l"(p));
    return a;
}
#define CPA16(dst, src) \
    asm volatile("cp.async.cg.shared.global [%0], [%1], 16;" :: "r"(dst), "l"(src))
#define CP_COMMIT() asm volatile("cp.async.commit_group;" ::: "memory")
#define CP_WAIT1()  asm volatile("cp.async.wait_group 1;" ::: "memory")

__device__ __forceinline__ void pack2(float x0, float x1, uint32_t& u0, uint32_t& u1) {
    __half a0 = __float2half_rn(x0), a1 = __float2half_rn(x1);
    float r0 = x0 - __half2float(a0), r1 = x1 - __half2float(a1);
    __half b0 = __float2half_rn(r0), b1 = __float2half_rn(r1);
    u0 = (uint32_t)__half_as_ushort(a0) | ((uint32_t)__half_as_ushort(a1) << 16);
    u1 = (uint32_t)__half_as_ushort(b0) | ((uint32_t)__half_as_ushort(b1) << 16);
}
__device__ __forceinline__ float unpack_half(uint32_t u, int hi) {
    return __half2float(__ushort_as_half((unsigned short)(hi ? (u >> 16) : (u & 0xffff))));
}
__device__ __forceinline__ void mma16(float* c, const uint32_t* a, const uint32_t* b) {
    asm volatile(
        "mma.sync.aligned.m16n8k16.row.col.f32.f16.f16.f32 "
        "{%0,%1,%2,%3}, {%4,%5,%6,%7}, {%8,%9}, {%0,%1,%2,%3};"
        : "+f"(c[0]), "+f"(c[1]), "+f"(c[2]), "+f"(c[3])
        : "r"(a[0]), "r"(a[1]), "r"(a[2]), "r"(a[3]), "r"(b[0]), "r"(b[1]));
}

// ---------------------------------------------------------------------------
// Paired GEMM (two same-shape C=A^T*B problems per launch; z>=B_ -> set1).
// EPI 2: packed hi/lo output (acc*packScale) via smem repack.
// EPI 4: fused logits epilogue: lpart[set][b][bx][n] =
//        sum_{c in tile} wv[c]*tanh(16*(Tp+Tph) + acc*outScale)
// ---------------------------------------------------------------------------
constexpr int SROW = 136;
constexpr int TILE_U = 16 * SROW;
constexpr int STG_U = 4 * TILE_U;
constexpr int SMEM_MMA = 3 * STG_U * 4;    // 104448 B

template <int EPI>
__global__ __launch_bounds__(256, 2)
void gemm_pair(const uint32_t* __restrict__ Ah0, const uint32_t* __restrict__ Al0,
               const uint32_t* __restrict__ Bh0, const uint32_t* __restrict__ Bl0,
               const uint32_t* __restrict__ Ah1, const uint32_t* __restrict__ Al1,
               const uint32_t* __restrict__ Bh1, const uint32_t* __restrict__ Bl1,
               int lda, size_t sA, size_t sB,
               uint32_t* __restrict__ Ph0, uint32_t* __restrict__ Pl0,
               uint32_t* __restrict__ Ph1, uint32_t* __restrict__ Pl1, size_t sP,
               const uint32_t* __restrict__ Tp0, const uint32_t* __restrict__ Tph0,
               const uint32_t* __restrict__ Tp1, const uint32_t* __restrict__ Tph1,
               const float* __restrict__ wv0, const float* __restrict__ wv1,
               float* __restrict__ lpart,
               int K, float outScale, float packScale)
{
    extern __shared__ __align__(16) uint32_t sm[];
    const int tid = threadIdx.x;
    const int bx = blockIdx.x, by = blockIdx.y;
    const int zraw = blockIdx.z;
    const bool sec = (zraw >= B_);
    const int bz = sec ? zraw - B_ : zraw;

    const uint32_t* Ah = sec ? Ah1 : Ah0;
    const uint32_t* Al = sec ? Al1 : Al0;
    const uint32_t* Bh = sec ? Bh1 : Bh0;
    const uint32_t* Bl = sec ? Bl1 : Bl0;

    const uint32_t* gAh = Ah + (size_t)bz * sA + by * 128;
    const uint32_t* gAl = Al + (size_t)bz * sA + by * 128;
    const uint32_t* gBh = Bh + (size_t)bz * sB + bx * 128;
    const uint32_t* gBl = Bl + (size_t)bz * sB + bx * 128;

    const int lane = tid & 31, w = tid >> 5;
    const int g = lane >> 2, t = lane & 3;
    const int rbase = (w & 1) * 64;
    const int cbase = (w >> 1) * 32;

    const uint32_t smb = smem_u32(sm);
    const int srow = tid >> 4;
    const int scol = (tid & 15) * 8;

    float c[4][4][4];
#pragma unroll
    for (int i = 0; i < 4; ++i)
#pragma unroll
        for (int j = 0; j < 4; ++j)
#pragma unroll
            for (int k = 0; k < 4; ++k) c[i][j][k] = 0.f;

    const int T = K >> 5;
    const uint32_t doff = (uint32_t)(srow * SROW + scol) * 4;

#define STAGE_LOADS(sidx, kp0) do {                                             \
    const uint32_t base_ = smb + (uint32_t)(sidx) * (STG_U * 4);                \
    const size_t kr_ = (size_t)((kp0) + srow);                                  \
    CPA16(base_ + doff,                    gAh + kr_ * lda + scol);             \
    CPA16(base_ + doff + 16,               gAh + kr_ * lda + scol + 4);         \
    CPA16(base_ + TILE_U*4 + doff,         gAl + kr_ * lda + scol);             \
    CPA16(base_ + TILE_U*4 + doff + 16,    gAl + kr_ * lda + scol + 4);         \
    CPA16(base_ + 2*TILE_U*4 + doff,       gBh + kr_ * 512 + scol);             \
    CPA16(base_ + 2*TILE_U*4 + doff + 16,  gBh + kr_ * 512 + scol + 4);         \
    CPA16(base_ + 3*TILE_U*4 + doff,       gBl + kr_ * 512 + scol);             \
    CPA16(base_ + 3*TILE_U*4 + doff + 16,  gBl + kr_ * 512 + scol + 4);         \
} while (0)

#pragma unroll
    for (int s = 0; s < 3; ++s) {
        STAGE_LOADS(s, s * 16);
        CP_COMMIT();
    }

    int buf = 0;
    for (int tt = 0; tt < T; ++tt) {
        CP_WAIT1();
        __syncthreads();

        const uint32_t* Ahs = sm + buf * STG_U;
        const uint32_t* Als = Ahs + TILE_U;
        const uint32_t* Bhs = Als + TILE_U;
        const uint32_t* Bls = Bhs + TILE_U;
#pragma unroll
        for (int ks = 0; ks < 2; ++ks) {
            const int kr = ks * 8 + t;
            const uint32_t* aph = Ahs + kr * SROW;
            const uint32_t* apl = Als + kr * SROW;
            const uint32_t* bph = Bhs + kr * SROW;
            const uint32_t* bpl = Bls + kr * SROW;
            uint32_t ah[4][4], al[4][4], bh[4][2], bl[4][2];
#pragma unroll
            for (int i = 0; i < 4; ++i) {
                const int m = rbase + i * 16 + g;
                ah[i][0] = aph[m];            al[i][0] = apl[m];
                ah[i][1] = aph[m + 8];        al[i][1] = apl[m + 8];
                ah[i][2] = aph[4*SROW + m];   al[i][2] = apl[4*SROW + m];
                ah[i][3] = aph[4*SROW + m+8]; al[i][3] = apl[4*SROW + m+8];
            }
#pragma unroll
            for (int j = 0; j < 4; ++j) {
                const int n = cbase + j * 8 + g;
                bh[j][0] = bph[n];            bl[j][0] = bpl[n];
                bh[j][1] = bph[4*SROW + n];   bl[j][1] = bpl[4*SROW + n];
            }
#pragma unroll
            for (int i = 0; i < 4; ++i)
#pragma unroll
                for (int j = 0; j < 4; ++j) {
                    mma16(c[i][j], ah[i], bl[j]);
                    mma16(c[i][j], al[i], bh[j]);
                    mma16(c[i][j], ah[i], bh[j]);
                }
        }
        __syncthreads();

        if (tt + 3 < T) STAGE_LOADS(buf, (tt + 3) * 16);
        CP_COMMIT();
        buf = (buf == 2) ? 0 : buf + 1;
    }
#undef STAGE_LOADS

    if (EPI & 2) {
        uint32_t* Ph = sec ? Ph1 : Ph0;
        uint32_t* Pl = sec ? Pl1 : Pl0;
        float* cs = reinterpret_cast<float*>(sm);
#pragma unroll
        for (int i = 0; i < 4; ++i) {
            const int r0 = rbase + i * 16 + g;
#pragma unroll
            for (int j = 0; j < 4; ++j) {
                const int cc = cbase + j * 8 + 2 * t;
                *reinterpret_cast<float2*>(cs + r0 * 132 + cc) =
                    make_float2(c[i][j][0], c[i][j][1]);
                *reinterpret_cast<float2*>(cs + (r0 + 8) * 132 + cc) =
                    make_float2(c[i][j][2], c[i][j][3]);
            }
        }
        __syncthreads();
        const size_t poff = (size_t)bz * sP + (size_t)(by * 64) * 512 + bx * 128;
#pragma unroll 4
        for (int it = 0; it < 32; ++it) {
            const int idx = it * 256 + tid;
            const int kp = idx >> 7, cc2 = idx & 127;
            const float x0 = cs[(2 * kp) * 132 + cc2] * packScale;
            const float x1 = cs[(2 * kp + 1) * 132 + cc2] * packScale;
            uint32_t u0, u1;
            pack2(x0, x1, u0, u1);
            Ph[poff + (size_t)kp * 512 + cc2] = u0;
            Pl[poff + (size_t)kp * 512 + cc2] = u1;
        }
    }
    if (EPI & 4) {
        // fused logits: M = acc*outScale in smem; T reconstructed from packed.
        const uint32_t* Tp  = sec ? Tp1  : Tp0;
        const uint32_t* Tph = sec ? Tph1 : Tph0;
        const float* wv = sec ? wv1 : wv0;
        float* cs = reinterpret_cast<float*>(sm);
#pragma unroll
        for (int i = 0; i < 4; ++i) {
            const int r0 = rbase + i * 16 + g;
#pragma unroll
            for (int j = 0; j < 4; ++j) {
                const int cc = cbase + j * 8 + 2 * t;
                *reinterpret_cast<float2*>(cs + r0 * 132 + cc) =
                    make_float2(c[i][j][0] * outScale, c[i][j][1] * outScale);
                *reinterpret_cast<float2*>(cs + (r0 + 8) * 132 + cc) =
                    make_float2(c[i][j][2] * outScale, c[i][j][3] * outScale);
            }
        }
        __syncthreads();
        const int c0 = lane * 4;                     // c within tile
        float wr[4];
#pragma unroll
        for (int k = 0; k < 4; ++k) wr[k] = wv[bx * 128 + c0 + k];
        float* lp = lpart + (((size_t)(sec ? B_ : 0) + bz) * 4 + bx) * 2048 + by * 128;
        for (int rl = 0; rl < 16; ++rl) {
            const int nl = w * 16 + rl;
            const int gn = by * 128 + nl;
            const size_t tb = (size_t)bz * sP + (size_t)(gn >> 1) * 512 + bx * 128 + c0;
            const uint4 q0 = *reinterpret_cast<const uint4*>(Tp + tb);
            const uint4 q1 = *reinterpret_cast<const uint4*>(Tph + tb);
            const int hi = gn & 1;
            float acc = 0.f;
            const uint32_t* a0 = reinterpret_cast<const uint32_t*>(&q0);
            const uint32_t* a1 = reinterpret_cast<const uint32_t*>(&q1);
#pragma unroll
            for (int k = 0; k < 4; ++k) {
                const float Tval = 16.f * (unpack_half(a0[k], hi) + unpack_half(a1[k], hi));
                acc += wr[k] * tanhf(Tval + cs[nl * 132 + c0 + k]);
            }
#pragma unroll
            for (int off = 16; off > 0; off >>= 1)
                acc += __shfl_down_sync(0xffffffffu, acc, off);
            if (lane == 0) lp[nl] = acc;
        }
    }
}

// --- dual pack: src[R][C] -> straight [R/2][C] AND transposed [C/2][R] ----
__global__ void dual_pack_k(const float* __restrict__ src,
                            uint32_t* __restrict__ sh0, uint32_t* __restrict__ sh1,
                            uint32_t* __restrict__ th0, uint32_t* __restrict__ th1,
                            int R, int C, size_t sS, size_t sSd, size_t sTd)
{
    __shared__ float tile[32][33];
    const size_t so = (size_t)blockIdx.z * sS;
    const int x0 = blockIdx.x * 32, y0 = blockIdx.y * 32;
    for (int j = threadIdx.y; j < 32; j += 8)
        tile[j][threadIdx.x] = src[so + (size_t)(y0 + j) * C + x0 + threadIdx.x];
    __syncthreads();
    const int tx = threadIdx.x;
    for (int kpl = threadIdx.y; kpl < 16; kpl += 8) {
        uint32_t u0, u1;
        pack2(tile[2 * kpl][tx], tile[2 * kpl + 1][tx], u0, u1);
        size_t o = (size_t)blockIdx.z * sSd + (size_t)(y0 / 2 + kpl) * C + x0 + tx;
        sh0[o] = u0; sh1[o] = u1;
        pack2(tile[tx][2 * kpl], tile[tx][2 * kpl + 1], u0, u1);
        o = (size_t)blockIdx.z * sTd + (size_t)(x0 / 2 + kpl) * R + y0 + tx;
        th0[o] = u0; th1[o] = u1;
    }
}

// --- transpose pack only ---------------------------------------------------
__global__ void tpack_k(const float* __restrict__ src, uint32_t* __restrict__ h0,
                        uint32_t* __restrict__ h1, int R, int C, size_t sS, size_t sD)
{
    __shared__ float tile[32][33];
    const size_t so = (size_t)blockIdx.z * sS;
    const int x0 = blockIdx.x * 32, y0 = blockIdx.y * 32;
    for (int j = threadIdx.y; j < 32; j += 8)
        tile[j][threadIdx.x] = src[so + (size_t)(y0 + j) * C + x0 + threadIdx.x];
    __syncthreads();
    const int tx = threadIdx.x;
    for (int kpl = threadIdx.y; kpl < 16; kpl += 8) {
        uint32_t u0, u1;
        pack2(tile[tx][2 * kpl], tile[tx][2 * kpl + 1], u0, u1);
        const size_t o = (size_t)blockIdx.z * sD + (size_t)(x0 / 2 + kpl) * R + y0 + tx;
        h0[o] = u0; h1[o] = u1;
    }
}

// ---- softmax over 2048 from 4 partial slices; blocks 0..15 set0, 16..31 set1
__global__ void softmax2(const float* __restrict__ lpart,
                         float* __restrict__ o0, float* __restrict__ o1, int Ncol)
{
    __shared__ float buf[2048];
    __shared__ float red[256];
    const bool sec = (blockIdx.x >= B_);
    const int b = sec ? blockIdx.x - B_ : blockIdx.x;
    const float* lp = lpart + (((size_t)(sec ? B_ : 0) + b) * 4) * 2048;
    float* outp = (sec ? o1 : o0) + (size_t)b * Ncol;
    const int tid = threadIdx.x;
    float mx = -INFINITY;
    for (int i = tid; i < Ncol; i += 256) {
        float v = lp[i] + lp[2048 + i] + lp[4096 + i] + lp[6144 + i];
        buf[i] = v;
        mx = fmaxf(mx, v);
    }
    red[tid] = mx; __syncthreads();
    for (int s = 128; s > 0; s >>= 1) { if (tid < s) red[tid] = fmaxf(red[tid], red[tid + s]); __syncthreads(); }
    mx = red[0]; __syncthreads();
    float sm = 0.f;
    for (int i = tid; i < Ncol; i += 256) { float e = expf(buf[i] - mx); buf[i] = e; sm += e; }
    red[tid] = sm; __syncthreads();
    for (int s = 128; s > 0; s >>= 1) { if (tid < s) red[tid] += red[tid + s]; __syncthreads(); }
    const float inv = 1.f / red[0];
    for (int i = tid; i < Ncol; i += 256) outp[i] = buf[i] * inv;
}

__global__ void wdot_kernel(const float* __restrict__ a, const float* __restrict__ X,
                            float* __restrict__ outv, int Ncol)
{
    const int b = blockIdx.y;
    const int h = blockIdx.x * 8 + (threadIdx.x >> 5);
    const int lane = threadIdx.x & 31;
    const float* row = X + ((size_t)b * H_ + h) * Ncol;
    const float* av = a + (size_t)b * Ncol;
    float acc = 0.f;
    for (int i = lane; i < Ncol; i += 32) acc += av[i] * row[i];
#pragma unroll
    for (int off = 16; off > 0; off >>= 1) acc += __shfl_down_sync(0xffffffffu, acc, off);
    if (lane == 0) outv[(size_t)b * H_ + h] = acc;
}

__global__ void aq_Q_partial(const float* __restrict__ a, const float* __restrict__ Q,
                             float* __restrict__ part)
{
    const int b = blockIdx.y, j = blockIdx.x;
    const int h = threadIdx.x;
    const float* aq = a + (size_t)b * NQ_;
    float acc = 0.f;
    const int q0 = j * (NQ_ / 16);
    for (int q = q0; q < q0 + NQ_ / 16; ++q)
        acc += aq[q] * Q[((size_t)b * NQ_ + q) * H_ + h];
    part[((size_t)b * 16 + j) * H_ + h] = acc;
}
__global__ void aq_Q_reduce(const float* __restrict__ part, float* __restrict__ outq)
{
    const int b = blockIdx.x;
    const int h = threadIdx.x;
    float acc = 0.f;
#pragma unroll
    for (int j = 0; j < 16; ++j)
        acc += part[((size_t)b * 16 + j) * H_ + h];
    outq[(size_t)b * H_ + h] = acc;
}

// ---------------------------------------------------------------------------
extern "C" void kernel_launch(void* const* d_in, const int* in_sizes, int n_in,
                              void* d_out, int out_size)
{
    const float* V    = (const float*)d_in[0];
    const float* Q    = (const float*)d_in[1];
    const float* W_b  = (const float*)d_in[2];
    const float* W_v  = (const float*)d_in[3];
    const float* W_q  = (const float*)d_in[4];
    const float* w_hv = (const float*)d_in[5];
    const float* w_hq = (const float*)d_in[6];
    float* out = (float*)d_out;

#define USYM(p, s) uint32_t* p; cudaGetSymbolAddress((void**)&p, s)
#define FSYM(p, s) float* p;    cudaGetSymbolAddress((void**)&p, s)
    USYM(Qp, g_Qp);     USYM(Qph, g_Qph);
    USYM(Qtp, g_Qtp);   USYM(Qtph, g_Qtph);
    USYM(Vp, g_Vp);     USYM(Vph, g_Vph);
    USYM(Vtp, g_Vtp);   USYM(Vtph, g_Vtph);
    USYM(Wbp, g_Wbp);   USYM(Wbph, g_Wbph);
    USYM(Wbtp, g_Wbtp); USYM(Wbtph, g_Wbtph);
    USYM(WqTp, g_WqTp); USYM(WqTph, g_WqTph);
    USYM(WvTp, g_WvTp); USYM(WvTph, g_WvTph);
    USYM(T1p, g_T1p);   USYM(T1ph, g_T1ph);
    USYM(T2p, g_T2p);   USYM(T2ph, g_T2ph);
    USYM(PvTp, g_PvTp); USYM(PvTph, g_PvTph);
    USYM(PqTp, g_PqTp); USYM(PqTph, g_PqTph);
    USYM(RvTp, g_RvTp); USYM(RvTph, g_RvTph);
    USYM(RqTp, g_RqTp); USYM(RqTph, g_RqTph);
    FSYM(lpart, g_lpart); FSYM(part, g_part);
#undef USYM
#undef FSYM

    cudaFuncSetAttribute(gemm_pair<2>, cudaFuncAttributeMaxDynamicSharedMemorySize, SMEM_MMA);
    cudaFuncSetAttribute(gemm_pair<4>, cudaFuncAttributeMaxDynamicSharedMemorySize, SMEM_MMA);

    const float S = 0.0625f;    // 1/16 intermediate pack scale
    const float R16 = 16.0f;

    // pre-pass
    dual_pack_k<<<dim3(H_/32, NQ_/32, B_), dim3(32, 8)>>>(Q, Qp, Qph, Qtp, Qtph, NQ_, H_,
                                                          (size_t)NQ_ * H_, PQ, PQT);
    dual_pack_k<<<dim3(NV_/32, H_/32, B_), dim3(32, 8)>>>(V, Vp, Vph, Vtp, Vtph, H_, NV_,
                                                          (size_t)H_ * NV_, PV, PVT);
    dual_pack_k<<<dim3(H_/32, H_/32, 1),  dim3(32, 8)>>>(W_b, Wbp, Wbph, Wbtp, Wbtph, H_, H_, 0, 0, 0);
    tpack_k<<<dim3(H_/32, CO_/32, 1), dim3(32, 8)>>>(W_q, WqTp, WqTph, CO_, H_, 0, 0);
    tpack_k<<<dim3(H_/32, CO_/32, 1), dim3(32, 8)>>>(W_v, WvTp, WvTph, CO_, H_, 0, 0);

    // pair1: G1 T1 = Qt^T·WqT | G2 T2 = V^T·WvT   [2048,512] K=1024  (packed only, scale 1/16)
    gemm_pair<2><<<dim3(4, NQ_/128, 2*B_), 256, SMEM_MMA>>>(
        Qtp, Qtph, WqTp, WqTph,   Vp, Vph, WvTp, WvTph,
        2048, PQT, 0,
        T1p, T1ph, T2p, T2ph, PNC,
        nullptr, nullptr, nullptr, nullptr, nullptr, nullptr, nullptr,
        H_, 1.f, S);
    // pair2: G3 PvT = Q^T·T1 | G6 PqT = Vt^T·T2   [1024,512] K=2048  (acc*16*(1/16)=acc)
    gemm_pair<2><<<dim3(4, H_/128, 2*B_), 256, SMEM_MMA>>>(
        Qp, Qph, T1p, T1ph,   Vtp, Vtph, T2p, T2ph,
        1024, PQ, PNC,
        PvTp, PvTph, PqTp, PqTph, PHC,
        nullptr, nullptr, nullptr, nullptr, nullptr, nullptr, nullptr,
        NQ_, R16, 1.f);
    // pair3: G4 RvT = Wb^T·PvT | G7 RqT = Wbt^T·PqT [1024,512] K=1024
    gemm_pair<2><<<dim3(4, H_/128, 2*B_), 256, SMEM_MMA>>>(
        Wbp, Wbph, PvTp, PvTph,   Wbtp, Wbtph, PqTp, PqTph,
        1024, 0, PHC,
        RvTp, RvTph, RqTp, RqTph, PHC,
        nullptr, nullptr, nullptr, nullptr, nullptr, nullptr, nullptr,
        H_, R16, 1.f);
    // pair4: G5 MvT = V^T·RvT | G8 MqT = Qt^T·RqT  [2048,512] K=1024
    //        fused logits vs T2p (set0) / T1p (set1); sP = PNC (T pack stride)
    gemm_pair<4><<<dim3(4, NV_/128, 2*B_), 256, SMEM_MMA>>>(
        Vp, Vph, RvTp, RvTph,   Qtp, Qtph, RqTp, RqTph,
        2048, PV, PHC,
        nullptr, nullptr, nullptr, nullptr, PNC,
        T2p, T2ph, T1p, T1ph, w_hv, w_hq, lpart,
        H_, R16, 0.f);

    float* out_av = out;
    float* out_aq = out + (size_t)B_ * NV_;
    float* out_v  = out + (size_t)B_ * (NV_ + NQ_);
    float* out_q  = out_v + (size_t)B_ * H_;

    softmax2<<<2 * B_, 256>>>(lpart, out_av, out_aq, NV_);

    wdot_kernel<<<dim3(H_/8, B_), 256>>>(out_av, V, out_v, NV_);
    aq_Q_partial<<<dim3(16, B_), 1024>>>(out_aq, Q, part);
    aq_Q_reduce<<<B_, 1024>>>(part, out_q);
}